// round 1
// baseline (speedup 1.0000x reference)
#include <cuda_runtime.h>

// TinyLocalWindowAttention fused kernel, fp32 baseline.
// x: (32, 256, 112, 112) f32 ; Wqkv: (256,256) ; bqkv: (256,) ; Wproj: (128,256) ; bproj: (256,)
// 112 % 7 == 0 -> no padding. 8192 windows of 49 tokens x 256 channels.
// One CTA per window, 256 threads. All intermediates in shared memory.

#define CCH   256      // channels
#define HH    112
#define WWID  112
#define WS    7
#define NT    49       // tokens per window
#define NH    4        // heads
#define KD    16       // key dim
#define DD    32       // value dim per head
#define XWS   258      // smem row stride (floats) for xw/qkv buffers (even, padded)
#define OS    130      // smem row stride for attention output o [49][128]

__global__ __launch_bounds__(256, 2)
void tiny_win_attn_kernel(const float* __restrict__ x,
                          const float* __restrict__ Wqkv,
                          const float* __restrict__ bqkv,
                          const float* __restrict__ Wproj,
                          const float* __restrict__ bproj,
                          float* __restrict__ out)
{
    extern __shared__ float smem[];
    float* xw  = smem;             // [49][XWS] window input, later reused as o [49][OS]
    float* qkv = smem + NT * XWS;  // [49][XWS] qkv, later reused as output staging
    float* o   = xw;               // reuse after qkv GEMM consumed xw

    const int tid = threadIdx.x;
    const int wid = blockIdx.x;        // 0..8191
    const int b   = wid >> 8;          // batch
    const int rem = wid & 255;
    const int wy  = rem >> 4;          // window row (0..15)
    const int wx  = rem & 15;          // window col (0..15)

    const size_t plane = (size_t)HH * WWID;
    const float* xbase = x + (size_t)b * CCH * plane + (size_t)(wy * WS) * WWID + wx * WS;

    // ---------------- Phase 1: load window -> smem xw[t][c] ----------------
    // 256 channels x 7 rows = 1792 row-segments of 7 contiguous floats.
    for (int idx = tid; idx < CCH * WS; idx += 256) {
        int c = idx / WS;
        int r = idx - c * WS;
        const float* src = xbase + (size_t)c * plane + (size_t)r * WWID;
        int t0 = r * WS;
        #pragma unroll
        for (int col = 0; col < WS; col++) {
            xw[(t0 + col) * XWS + c] = src[col];
        }
    }
    __syncthreads();

    // ---------------- Phase 2: qkv = xw @ Wqkv + bqkv ----------------
    // thread j computes column j for all 49 tokens.
    {
        const int j = tid;
        float acc[NT];
        const float bj = bqkv[j];
        #pragma unroll
        for (int t = 0; t < NT; t++) acc[t] = bj;

        for (int k = 0; k < CCH; k += 4) {
            const float w0 = Wqkv[(k + 0) * CCH + j];
            const float w1 = Wqkv[(k + 1) * CCH + j];
            const float w2 = Wqkv[(k + 2) * CCH + j];
            const float w3 = Wqkv[(k + 3) * CCH + j];
            #pragma unroll
            for (int t = 0; t < NT; t++) {
                const float2* p = (const float2*)&xw[t * XWS + k];
                float2 a = p[0];
                float2 c2 = p[1];
                acc[t] = fmaf(a.x,  w0, acc[t]);
                acc[t] = fmaf(a.y,  w1, acc[t]);
                acc[t] = fmaf(c2.x, w2, acc[t]);
                acc[t] = fmaf(c2.y, w3, acc[t]);
            }
        }
        #pragma unroll
        for (int t = 0; t < NT; t++) qkv[t * XWS + j] = acc[t];
    }
    __syncthreads();

    // ---------------- Phase 3: attention (4 heads x 49 queries = 196 threads) ----------------
    // qkv columns: q = [0,64), k = [64,128), v = [128,256)
    if (tid < NH * NT) {
        const int h = tid / NT;
        const int n = tid - h * NT;

        float qreg[KD];
        {
            const float* qn = &qkv[n * XWS + h * KD];
            #pragma unroll
            for (int i = 0; i < KD; i++) qreg[i] = qn[i];
        }

        float s[NT];
        float mx = -1e30f;
        for (int m = 0; m < NT; m++) {
            const float* km = &qkv[m * XWS + 64 + h * KD];
            float a = 0.0f;
            #pragma unroll
            for (int i = 0; i < KD; i++) a = fmaf(qreg[i], km[i], a);
            a *= 0.25f;   // KEY_DIM^-0.5 = 16^-0.5
            s[m] = a;
            mx = fmaxf(mx, a);
        }
        float sum = 0.0f;
        for (int m = 0; m < NT; m++) {
            float e = __expf(s[m] - mx);
            s[m] = e;
            sum += e;
        }
        const float inv = 1.0f / sum;

        float od[DD];
        #pragma unroll
        for (int d = 0; d < DD; d++) od[d] = 0.0f;
        for (int m = 0; m < NT; m++) {
            const float p = s[m] * inv;
            const float* vm = &qkv[m * XWS + 128 + h * DD];
            #pragma unroll
            for (int d = 0; d < DD; d++) od[d] = fmaf(p, vm[d], od[d]);
        }
        float* on = &o[n * OS + h * DD];
        #pragma unroll
        for (int d = 0; d < DD; d++) on[d] = od[d];
    }
    __syncthreads();

    // ---------------- Phase 4: proj: res = o @ Wproj + bproj ----------------
    {
        const int j = tid;
        float acc[NT];
        const float bj = bproj[j];
        #pragma unroll
        for (int t = 0; t < NT; t++) acc[t] = bj;

        for (int k = 0; k < NH * DD; k += 4) {
            const float w0 = Wproj[(k + 0) * CCH + j];
            const float w1 = Wproj[(k + 1) * CCH + j];
            const float w2 = Wproj[(k + 2) * CCH + j];
            const float w3 = Wproj[(k + 3) * CCH + j];
            #pragma unroll
            for (int t = 0; t < NT; t++) {
                const float2* p = (const float2*)&o[t * OS + k];
                float2 a = p[0];
                float2 c2 = p[1];
                acc[t] = fmaf(a.x,  w0, acc[t]);
                acc[t] = fmaf(a.y,  w1, acc[t]);
                acc[t] = fmaf(c2.x, w2, acc[t]);
                acc[t] = fmaf(c2.y, w3, acc[t]);
            }
        }
        // stage into qkv region for coalesced store
        #pragma unroll
        for (int t = 0; t < NT; t++) qkv[t * XWS + j] = acc[t];
    }
    __syncthreads();

    // ---------------- Phase 5: store window ----------------
    float* obase = out + (size_t)b * CCH * plane + (size_t)(wy * WS) * WWID + wx * WS;
    for (int idx = tid; idx < CCH * WS; idx += 256) {
        int c = idx / WS;
        int r = idx - c * WS;
        float* dst = obase + (size_t)c * plane + (size_t)r * WWID;
        int t0 = r * WS;
        #pragma unroll
        for (int col = 0; col < WS; col++) {
            dst[col] = qkv[(t0 + col) * XWS + c];
        }
    }
}

extern "C" void kernel_launch(void* const* d_in, const int* in_sizes, int n_in,
                              void* d_out, int out_size)
{
    (void)in_sizes; (void)n_in; (void)out_size;
    const float* x     = (const float*)d_in[0];
    const float* Wqkv  = (const float*)d_in[1];
    const float* bqkv  = (const float*)d_in[2];
    const float* Wproj = (const float*)d_in[3];
    const float* bproj = (const float*)d_in[4];
    float* out = (float*)d_out;

    const int smem_bytes = 2 * NT * XWS * (int)sizeof(float);  // 101,136 B
    static bool attr_set = false;
    if (!attr_set) {
        cudaFuncSetAttribute(tiny_win_attn_kernel,
                             cudaFuncAttributeMaxDynamicSharedMemorySize, smem_bytes);
        attr_set = true;
    }

    dim3 grid(8192);
    dim3 block(256);
    tiny_win_attn_kernel<<<grid, block, smem_bytes>>>(x, Wqkv, bqkv, Wproj, bproj, out);
}

// round 4
// speedup vs baseline: 1.1612x; 1.1612x over previous
#include <cuda_runtime.h>
#include <cstdint>

// TinyLocalWindowAttention fused kernel, fp32 with f32x2 packed FMA.
// x: (32, 256, 112, 112) f32 ; Wqkv: (256,256) ; bqkv: (256,) ; Wproj: (128,256) ; bproj: (256,)
// 8192 windows of 49 tokens x 256 channels. One CTA per window, 256 threads.

#define CCH   256      // channels
#define HH    112
#define WWID  112
#define WS    7
#define NT    49       // tokens per window
#define NH    4        // heads
#define KD    16       // key dim
#define DD    32       // value dim per head
#define XWS   258      // smem row stride (floats), even

__device__ __forceinline__ uint64_t pack2(float lo, float hi) {
    uint64_t r;
    asm("mov.b64 %0, {%1, %2};" : "=l"(r) : "f"(lo), "f"(hi));
    return r;
}
__device__ __forceinline__ void unpack2(uint64_t p, float& lo, float& hi) {
    asm("mov.b64 {%0, %1}, %2;" : "=f"(lo), "=f"(hi) : "l"(p));
}
__device__ __forceinline__ void ffma2(uint64_t& d, uint64_t a, uint64_t b) {
    asm("fma.rn.f32x2 %0, %1, %2, %0;" : "+l"(d) : "l"(a), "l"(b));
}

__global__ __launch_bounds__(256, 2)
void tiny_win_attn_kernel(const float* __restrict__ x,
                          const float* __restrict__ Wqkv,
                          const float* __restrict__ bqkv,
                          const float* __restrict__ Wproj,
                          const float* __restrict__ bproj,
                          float* __restrict__ out)
{
    extern __shared__ float smem[];
    float* xw  = smem;             // [49][XWS] window input; reused as o after phase 3
    float* qkv = smem + NT * XWS;  // [49][XWS] qkv; reused as output staging
    float* o   = xw;

    const int tid = threadIdx.x;
    const int wid = blockIdx.x;        // 0..8191
    const int b   = wid >> 8;
    const int rem = wid & 255;
    const int wy  = rem >> 4;
    const int wx  = rem & 15;

    const size_t plane = (size_t)HH * WWID;
    const float* xbase = x + (size_t)b * CCH * plane + (size_t)(wy * WS) * WWID + wx * WS;

    // ---------------- Phase 1: load window -> smem xw[t][c] ----------------
    for (int idx = tid; idx < CCH * WS; idx += 256) {
        int c = idx / WS;
        int r = idx - c * WS;
        const float* src = xbase + (size_t)c * plane + (size_t)r * WWID;
        int t0 = r * WS;
        #pragma unroll
        for (int col = 0; col < WS; col++) {
            xw[(t0 + col) * XWS + c] = src[col];
        }
    }
    __syncthreads();

    // ---------------- Phase 2: qkv = xw @ Wqkv + bqkv ----------------
    // 224 threads: warp = token group (7 tokens), lane = column group (8 cols).
    // xw reads are warp-uniform (LDS broadcast). W pairs via f32x2.
    if (tid < 224) {
        const int tg = tid >> 5;          // 0..6 (warp id)
        const int cg = tid & 31;          // 0..31
        const int t0 = tg * WS;           // token base
        const int j0 = cg * 8;            // column base

        uint64_t acc[WS][4];
        {
            const float2* bp = (const float2*)(bqkv + j0);
            float2 b0 = bp[0], b1 = bp[1], b2 = bp[2], b3 = bp[3];
            #pragma unroll
            for (int tm = 0; tm < WS; tm++) {
                acc[tm][0] = pack2(b0.x, b0.y);
                acc[tm][1] = pack2(b1.x, b1.y);
                acc[tm][2] = pack2(b2.x, b2.y);
                acc[tm][3] = pack2(b3.x, b3.y);
            }
        }
        const float* wrow = Wqkv + j0;
        const float* xrow = xw + t0 * XWS;
        #pragma unroll 2
        for (int k = 0; k < CCH; k++) {
            const ulonglong2* wp = (const ulonglong2*)wrow;
            ulonglong2 wa = wp[0];
            ulonglong2 wb = wp[1];
            #pragma unroll
            for (int tm = 0; tm < WS; tm++) {
                float xs = xrow[tm * XWS + k];
                uint64_t xp = pack2(xs, xs);
                ffma2(acc[tm][0], xp, wa.x);
                ffma2(acc[tm][1], xp, wa.y);
                ffma2(acc[tm][2], xp, wb.x);
                ffma2(acc[tm][3], xp, wb.y);
            }
            wrow += CCH;
        }
        #pragma unroll
        for (int tm = 0; tm < WS; tm++) {
            uint64_t* dst = (uint64_t*)(qkv + (t0 + tm) * XWS + j0);
            dst[0] = acc[tm][0];
            dst[1] = acc[tm][1];
            dst[2] = acc[tm][2];
            dst[3] = acc[tm][3];
        }
    }
    __syncthreads();

    // ---------------- Phase 3: attention (4 heads x 49 queries) ----------------
    // qkv columns: q = [0,64), k = [64,128), v = [128,256)
    if (tid < NH * NT) {
        const int h = tid / NT;
        const int n = tid - h * NT;

        uint64_t q2[KD / 2];
        {
            const uint64_t* qp = (const uint64_t*)&qkv[n * XWS + h * KD];
            #pragma unroll
            for (int i = 0; i < KD / 2; i++) q2[i] = qp[i];
        }

        float s[NT];
        float mx = -1e30f;
        for (int m = 0; m < NT; m++) {
            const uint64_t* km = (const uint64_t*)&qkv[m * XWS + 64 + h * KD];
            uint64_t a2 = pack2(0.0f, 0.0f);
            #pragma unroll
            for (int i = 0; i < KD / 2; i++) ffma2(a2, q2[i], km[i]);
            float alo, ahi;
            unpack2(a2, alo, ahi);
            float a = (alo + ahi) * 0.25f;   // KEY_DIM^-0.5
            s[m] = a;
            mx = fmaxf(mx, a);
        }
        float sum = 0.0f;
        for (int m = 0; m < NT; m++) {
            float e = __expf(s[m] - mx);
            s[m] = e;
            sum += e;
        }
        const float inv = 1.0f / sum;

        uint64_t od2[DD / 2];
        #pragma unroll
        for (int d = 0; d < DD / 2; d++) od2[d] = pack2(0.0f, 0.0f);
        for (int m = 0; m < NT; m++) {
            const float p = s[m] * inv;
            uint64_t pp = pack2(p, p);
            const uint64_t* vm = (const uint64_t*)&qkv[m * XWS + 128 + h * DD];
            #pragma unroll
            for (int d = 0; d < DD / 2; d++) ffma2(od2[d], pp, vm[d]);
        }
        uint64_t* on = (uint64_t*)&o[n * XWS + h * DD];
        #pragma unroll
        for (int d = 0; d < DD / 2; d++) on[d] = od2[d];
    }
    __syncthreads();

    // ---------------- Phase 4: proj: res = o @ Wproj + bproj ----------------
    if (tid < 224) {
        const int tg = tid >> 5;
        const int cg = tid & 31;
        const int t0 = tg * WS;
        const int j0 = cg * 8;

        uint64_t acc[WS][4];
        {
            const float2* bp = (const float2*)(bproj + j0);
            float2 b0 = bp[0], b1 = bp[1], b2 = bp[2], b3 = bp[3];
            #pragma unroll
            for (int tm = 0; tm < WS; tm++) {
                acc[tm][0] = pack2(b0.x, b0.y);
                acc[tm][1] = pack2(b1.x, b1.y);
                acc[tm][2] = pack2(b2.x, b2.y);
                acc[tm][3] = pack2(b3.x, b3.y);
            }
        }
        const float* wrow = Wproj + j0;
        const float* orow = o + t0 * XWS;
        #pragma unroll 2
        for (int k = 0; k < NH * DD; k++) {
            const ulonglong2* wp = (const ulonglong2*)wrow;
            ulonglong2 wa = wp[0];
            ulonglong2 wb = wp[1];
            #pragma unroll
            for (int tm = 0; tm < WS; tm++) {
                float xs = orow[tm * XWS + k];
                uint64_t xp = pack2(xs, xs);
                ffma2(acc[tm][0], xp, wa.x);
                ffma2(acc[tm][1], xp, wa.y);
                ffma2(acc[tm][2], xp, wb.x);
                ffma2(acc[tm][3], xp, wb.y);
            }
            wrow += CCH;
        }
        #pragma unroll
        for (int tm = 0; tm < WS; tm++) {
            uint64_t* dst = (uint64_t*)(qkv + (t0 + tm) * XWS + j0);
            dst[0] = acc[tm][0];
            dst[1] = acc[tm][1];
            dst[2] = acc[tm][2];
            dst[3] = acc[tm][3];
        }
    }
    __syncthreads();

    // ---------------- Phase 5: store window ----------------
    float* obase = out + (size_t)b * CCH * plane + (size_t)(wy * WS) * WWID + wx * WS;
    for (int idx = tid; idx < CCH * WS; idx += 256) {
        int c = idx / WS;
        int r = idx - c * WS;
        float* dst = obase + (size_t)c * plane + (size_t)r * WWID;
        int t0 = r * WS;
        #pragma unroll
        for (int col = 0; col < WS; col++) {
            dst[col] = qkv[(t0 + col) * XWS + c];
        }
    }
}

extern "C" void kernel_launch(void* const* d_in, const int* in_sizes, int n_in,
                              void* d_out, int out_size)
{
    (void)in_sizes; (void)n_in; (void)out_size;
    const float* x     = (const float*)d_in[0];
    const float* Wqkv  = (const float*)d_in[1];
    const float* bqkv  = (const float*)d_in[2];
    const float* Wproj = (const float*)d_in[3];
    const float* bproj = (const float*)d_in[4];
    float* out = (float*)d_out;

    const int smem_bytes = 2 * NT * XWS * (int)sizeof(float);  // 101,136 B
    static bool attr_set = false;
    if (!attr_set) {
        cudaFuncSetAttribute(tiny_win_attn_kernel,
                             cudaFuncAttributeMaxDynamicSharedMemorySize, smem_bytes);
        attr_set = true;
    }

    dim3 grid(8192);
    dim3 block(256);
    tiny_win_attn_kernel<<<grid, block, smem_bytes>>>(x, Wqkv, bqkv, Wproj, bproj, out);
}

// round 15
// speedup vs baseline: 1.3745x; 1.1837x over previous
#include <cuda_runtime.h>
#include <cuda_bf16.h>
#include <cstdint>

// ========== TinyLocalWindowAttention — mma.sync (HMMA) bf16 split-precision ==========
// tcgen05 unavailable (harness targets sm_103 without 'a'); use sm_80+ mma.sync path.
// x:(32,256,112,112) f32. 8192 windows of 49 tok x 256 ch. 1 window/CTA, M=64 (49 used).
// GEMMs: qkv [64x256]x[256x256], proj [64x128]x[128x256], 3-term bf16 split, fp32 acc.

#define CCH    256
#define PLANE  (112*112)
#define NT     49
#define THREADS 256

#define XWST   264        // bf16 stride for A/B tiles (row = 528 B)
#define OST    136        // bf16 stride for o tile (row = 272 B)
#define QBST   264        // f32 stride for qkv/proj buffer

// smem byte offsets
#define OFF_XH 0                         // xw_hi [64][264] bf16 = 33792
#define OFF_XL 33792                     // xw_lo
#define OFF_BH 67584                     // B_hi  [64][264] bf16
#define OFF_BL 101376                    // B_lo
#define OFF_QB 135168                    // qkvbuf/projbuf [49][264] f32 = 51744
#define SMEM_TOTAL (OFF_QB + 51744)      // 186912
// overlays after qkv (xw region dead):
#define OFF_OH 0                         // o_hi [64][136] bf16 = 17408
#define OFF_OL 17408                     // o_lo

// ---- weights: W^T split to bf16 hi/lo, row-major [n][k] ----
__device__ __align__(16) __nv_bfloat16 g_wq_hi[256*256];
__device__ __align__(16) __nv_bfloat16 g_wq_lo[256*256];
__device__ __align__(16) __nv_bfloat16 g_wp_hi[256*128];
__device__ __align__(16) __nv_bfloat16 g_wp_lo[256*128];

__device__ __forceinline__ uint32_t smem_u32(const void* p) {
    uint32_t a;
    asm("{ .reg .u64 t; cvta.to.shared.u64 t, %1; cvt.u32.u64 %0, t; }" : "=r"(a) : "l"(p));
    return a;
}
__device__ __forceinline__ void ldsm4(uint32_t* r, uint32_t addr) {
    asm volatile("ldmatrix.sync.aligned.m8n8.x4.shared.b16 {%0,%1,%2,%3}, [%4];"
                 : "=r"(r[0]), "=r"(r[1]), "=r"(r[2]), "=r"(r[3]) : "r"(addr));
}
__device__ __forceinline__ void mma_bf16(float* d, const uint32_t* a, const uint32_t* b) {
    asm volatile(
        "mma.sync.aligned.m16n8k16.row.col.f32.bf16.bf16.f32 "
        "{%0,%1,%2,%3}, {%4,%5,%6,%7}, {%8,%9}, {%0,%1,%2,%3};"
        : "+f"(d[0]), "+f"(d[1]), "+f"(d[2]), "+f"(d[3])
        : "r"(a[0]), "r"(a[1]), "r"(a[2]), "r"(a[3]), "r"(b[0]), "r"(b[1]));
}

// ================= prep kernel: W^T + bf16 split =================
__global__ void prep_kernel(const float* __restrict__ Wqkv, const float* __restrict__ Wproj)
{
    int i = blockIdx.x * 256 + threadIdx.x;
    if (i < 65536) {                      // g_wq[j][k] = Wqkv[k][j]
        int j = i >> 8, k = i & 255;
        float w = Wqkv[k * 256 + j];
        __nv_bfloat16 h = __float2bfloat16(w);
        g_wq_hi[i] = h;
        g_wq_lo[i] = __float2bfloat16(w - __bfloat162float(h));
    } else if (i < 65536 + 32768) {       // g_wp[j][k] = Wproj[k][j]
        int t = i - 65536;
        int j = t >> 7, k = t & 127;
        float w = Wproj[k * 256 + j];
        __nv_bfloat16 h = __float2bfloat16(w);
        g_wp_hi[t] = h;
        g_wp_lo[t] = __float2bfloat16(w - __bfloat162float(h));
    }
}

// ================= main kernel =================
__global__ __launch_bounds__(THREADS, 1)
void tiny_win_attn_mma(const float* __restrict__ x,
                       const float* __restrict__ bqkv,
                       const float* __restrict__ bproj,
                       float* __restrict__ out)
{
    extern __shared__ char smem8[];
    const uint32_t sb = smem_u32(smem8);
    const int tid  = threadIdx.x;
    const int wid  = tid >> 5;
    const int lane = tid & 31;
    const int wm   = wid & 3;       // m-block (rows 16*wm)
    const int wn   = wid >> 2;      // n-group within 64-chunk (cols 32*wn)

    // ldmatrix lane addressing
    const int lrow = (lane & 7) + ((lane >> 3) & 1) * 8;   // A row within 16
    const int lk   = (lane >> 4) * 8;                      // A k offset within 16
    const int bn   = (lane & 7) + ((lane >> 4) & 1) * 8;   // B n within 16
    const int bk   = ((lane >> 3) & 1) * 8;                // B k offset within 16

    const int w  = blockIdx.x;
    const int b  = w >> 8;
    const int wy = (w & 255) >> 4;
    const int wx = w & 15;

    float* qb = (float*)(smem8 + OFF_QB);

    // ---- Phase 1: gather x -> xw_hi/xw_lo (rows=token 0..48, cols=channel) ----
    for (int e = tid; e < CCH * 7; e += THREADS) {
        int c = e / 7, r = e - c * 7;
        const float* src = x + ((size_t)b * CCH + c) * PLANE + (size_t)(wy * 7 + r) * 112 + wx * 7;
        #pragma unroll
        for (int col = 0; col < 7; col++) {
            float v = src[col];
            __nv_bfloat16 h = __float2bfloat16(v);
            __nv_bfloat16 l = __float2bfloat16(v - __bfloat162float(h));
            int t = r * 7 + col;
            *(__nv_bfloat16*)(smem8 + OFF_XH + t * (XWST * 2) + c * 2) = h;
            *(__nv_bfloat16*)(smem8 + OFF_XL + t * (XWST * 2) + c * 2) = l;
        }
    }

    // ---- Phase 2: qkv = xw @ Wqkv + bqkv (N chunks of 64, K=256) ----
    for (int c = 0; c < 4; c++) {
        __syncthreads();
        // stage B chunk: rows n = c*64 .. +63, k = 0..255, hi+lo
        for (int e = tid; e < 64 * 32; e += THREADS) {
            int rl = e >> 5, kc = (e & 31) << 3;
            size_t gi = (size_t)(c * 64 + rl) * 256 + kc;
            uint32_t so = (uint32_t)(rl * (XWST * 2) + kc * 2);
            *(uint4*)(smem8 + OFF_BH + so) = *(const uint4*)(g_wq_hi + gi);
            *(uint4*)(smem8 + OFF_BL + so) = *(const uint4*)(g_wq_lo + gi);
        }
        __syncthreads();

        float acc[4][4];
        #pragma unroll
        for (int s4 = 0; s4 < 4; s4++)
            #pragma unroll
            for (int j = 0; j < 4; j++) acc[s4][j] = 0.0f;

        #pragma unroll 2
        for (int s = 0; s < 16; s++) {
            uint32_t ah[4], al[4];
            uint32_t aoff = (uint32_t)((16 * wm + lrow) * (XWST * 2) + (16 * s + lk) * 2);
            ldsm4(ah, sb + OFF_XH + aoff);
            ldsm4(al, sb + OFF_XL + aoff);
            #pragma unroll
            for (int p = 0; p < 2; p++) {
                uint32_t bh[4], bl[4];
                uint32_t boff = (uint32_t)((wn * 32 + 16 * p + bn) * (XWST * 2) + (16 * s + bk) * 2);
                ldsm4(bh, sb + OFF_BH + boff);
                ldsm4(bl, sb + OFF_BL + boff);
                mma_bf16(acc[2 * p],     ah, bh);
                mma_bf16(acc[2 * p],     ah, bl);
                mma_bf16(acc[2 * p],     al, bh);
                mma_bf16(acc[2 * p + 1], ah, bh + 2);
                mma_bf16(acc[2 * p + 1], ah, bl + 2);
                mma_bf16(acc[2 * p + 1], al, bh + 2);
            }
        }
        // store acc (+bias) to qb
        {
            int r0 = wm * 16 + (lane >> 2);
            int jb = c * 64 + wn * 32;
            #pragma unroll
            for (int sub = 0; sub < 4; sub++) {
                int col = jb + sub * 8 + 2 * (lane & 3);
                float b0 = __ldg(&bqkv[col]), b1 = __ldg(&bqkv[col + 1]);
                if (r0 < NT) {
                    qb[r0 * QBST + col]     = acc[sub][0] + b0;
                    qb[r0 * QBST + col + 1] = acc[sub][1] + b1;
                }
                if (r0 + 8 < NT) {
                    qb[(r0 + 8) * QBST + col]     = acc[sub][2] + b0;
                    qb[(r0 + 8) * QBST + col + 1] = acc[sub][3] + b1;
                }
            }
        }
    }
    __syncthreads();

    // ---- Phase 3: attention (4 heads x 49 queries = 196 tasks) ----
    // qb cols: q=[0,64), k=[64,128), v=[128,256)
    if (tid < 4 * NT) {
        const int h = tid / NT;
        const int n = tid - h * NT;
        float q[16];
        #pragma unroll
        for (int i = 0; i < 16; i++) q[i] = qb[n * QBST + h * 16 + i];
        float s[NT];
        float mx = -1e30f;
        for (int m = 0; m < NT; m++) {
            const float* km = &qb[m * QBST + 64 + h * 16];
            float a = 0.0f;
            #pragma unroll
            for (int i = 0; i < 16; i++) a = fmaf(q[i], km[i], a);
            a *= 0.25f;
            s[m] = a;
            mx = fmaxf(mx, a);
        }
        float sum = 0.0f;
        for (int m = 0; m < NT; m++) { float e = __expf(s[m] - mx); s[m] = e; sum += e; }
        const float inv = 1.0f / sum;
        float od[32];
        #pragma unroll
        for (int d = 0; d < 32; d++) od[d] = 0.0f;
        for (int m = 0; m < NT; m++) {
            const float pm = s[m] * inv;
            const float* vm = &qb[m * QBST + 128 + h * 32];
            #pragma unroll
            for (int d = 0; d < 32; d++) od[d] = fmaf(pm, vm[d], od[d]);
        }
        // write o tile (bf16 hi/lo), row n, col h*32+d
        #pragma unroll
        for (int d = 0; d < 32; d++) {
            float v = od[d];
            __nv_bfloat16 hi = __float2bfloat16(v);
            __nv_bfloat16 lo = __float2bfloat16(v - __bfloat162float(hi));
            uint32_t o = (uint32_t)(n * (OST * 2) + (h * 32 + d) * 2);
            *(__nv_bfloat16*)(smem8 + OFF_OH + o) = hi;
            *(__nv_bfloat16*)(smem8 + OFF_OL + o) = lo;
        }
    }

    // ---- Phase 4: proj = o @ Wproj + bproj (N chunks of 64, K=128) ----
    for (int c = 0; c < 4; c++) {
        __syncthreads();
        for (int e = tid; e < 64 * 16; e += THREADS) {
            int rl = e >> 4, kc = (e & 15) << 3;
            size_t gi = (size_t)(c * 64 + rl) * 128 + kc;
            uint32_t so = (uint32_t)(rl * (XWST * 2) + kc * 2);
            *(uint4*)(smem8 + OFF_BH + so) = *(const uint4*)(g_wp_hi + gi);
            *(uint4*)(smem8 + OFF_BL + so) = *(const uint4*)(g_wp_lo + gi);
        }
        __syncthreads();

        float acc[4][4];
        #pragma unroll
        for (int s4 = 0; s4 < 4; s4++)
            #pragma unroll
            for (int j = 0; j < 4; j++) acc[s4][j] = 0.0f;

        #pragma unroll 2
        for (int s = 0; s < 8; s++) {
            uint32_t ah[4], al[4];
            uint32_t aoff = (uint32_t)((16 * wm + lrow) * (OST * 2) + (16 * s + lk) * 2);
            ldsm4(ah, sb + OFF_OH + aoff);
            ldsm4(al, sb + OFF_OL + aoff);
            #pragma unroll
            for (int p = 0; p < 2; p++) {
                uint32_t bh[4], bl[4];
                uint32_t boff = (uint32_t)((wn * 32 + 16 * p + bn) * (XWST * 2) + (16 * s + bk) * 2);
                ldsm4(bh, sb + OFF_BH + boff);
                ldsm4(bl, sb + OFF_BL + boff);
                mma_bf16(acc[2 * p],     ah, bh);
                mma_bf16(acc[2 * p],     ah, bl);
                mma_bf16(acc[2 * p],     al, bh);
                mma_bf16(acc[2 * p + 1], ah, bh + 2);
                mma_bf16(acc[2 * p + 1], ah, bl + 2);
                mma_bf16(acc[2 * p + 1], al, bh + 2);
            }
        }
        {
            int r0 = wm * 16 + (lane >> 2);
            int jb = c * 64 + wn * 32;
            #pragma unroll
            for (int sub = 0; sub < 4; sub++) {
                int col = jb + sub * 8 + 2 * (lane & 3);
                float b0 = __ldg(&bproj[col]), b1 = __ldg(&bproj[col + 1]);
                if (r0 < NT) {
                    qb[r0 * QBST + col]     = acc[sub][0] + b0;
                    qb[r0 * QBST + col + 1] = acc[sub][1] + b1;
                }
                if (r0 + 8 < NT) {
                    qb[(r0 + 8) * QBST + col]     = acc[sub][2] + b0;
                    qb[(r0 + 8) * QBST + col + 1] = acc[sub][3] + b1;
                }
            }
        }
    }
    __syncthreads();

    // ---- Phase 5: store window (coalesced 7-float rows per channel) ----
    for (int e = tid; e < CCH * 7; e += THREADS) {
        int c = e / 7, r = e - c * 7;
        float* dst = out + ((size_t)b * CCH + c) * PLANE + (size_t)(wy * 7 + r) * 112 + wx * 7;
        #pragma unroll
        for (int col = 0; col < 7; col++) {
            dst[col] = qb[(r * 7 + col) * QBST + c];
        }
    }
}

// ================= launch =================
extern "C" void kernel_launch(void* const* d_in, const int* in_sizes, int n_in,
                              void* d_out, int out_size)
{
    (void)in_sizes; (void)n_in; (void)out_size;
    const float* x     = (const float*)d_in[0];
    const float* Wqkv  = (const float*)d_in[1];
    const float* bqkv  = (const float*)d_in[2];
    const float* Wproj = (const float*)d_in[3];
    const float* bproj = (const float*)d_in[4];
    float* out = (float*)d_out;

    static bool attr_set = false;
    if (!attr_set) {
        cudaFuncSetAttribute(tiny_win_attn_mma,
                             cudaFuncAttributeMaxDynamicSharedMemorySize, SMEM_TOTAL);
        attr_set = true;
    }

    prep_kernel<<<384, 256>>>(Wqkv, Wproj);
    tiny_win_attn_mma<<<8192, THREADS, SMEM_TOTAL>>>(x, bqkv, bproj, out);
}